// round 16
// baseline (speedup 1.0000x reference)
#include <cuda_runtime.h>
#include <cuda_bf16.h>
#include <cstdint>

#define HN    32
#define KP    15
#define CIN   128
#define COUT  128
#define KTOT  1920          // KP * CIN
#define M_MAX 50000
#define CAP   50176         // per-k capacity (row stride in compacted buffers)
#define GRIDX 160           // gemm x-tiles per k (10240 rows >> max possible ~6700)
#define TR    64            // gemm tile rows
#define MAXR  (GRIDX * TR)  // rows the gemm can consume per k

// ---- device scratch (static __device__ arrays: the sanctioned no-alloc path) ----
__device__ __nv_bfloat16 g_a_hi[(size_t)KP * CAP * CIN];  // compacted hi rows
__device__ __nv_bfloat16 g_a_lo[(size_t)KP * CAP * CIN];  // compacted lo rows
__device__ float         g_part[(size_t)KP * CAP * COUT]; // per-k GEMM partials (385MB)
__device__ uint32_t      g_kmask[CAP];                    // active-k bitmap per query
__device__ int           g_rkmap[(size_t)CAP * 16];       // rank of (m,k) plane
__device__ int           g_cnt[16];                       // rows appended per k
__device__ __nv_bfloat16 g_wt_hi[COUT * KTOT];            // W^T [d][kk] bf16 hi
__device__ __nv_bfloat16 g_wt_lo[COUT * KTOT];            // W^T [d][kk] bf16 lo
__device__ float4        g_pts4[CAP];                     // padded support points

__device__ __forceinline__ uint32_t smem_u32(const void* p) {
    uint32_t a;
    asm("{ .reg .u64 t; cvta.to.shared.u64 t, %1; cvt.u32.u64 %0, t; }" : "=r"(a) : "l"(p));
    return a;
}
__device__ __forceinline__ void cp16(uint32_t dst, const void* src) {
    asm volatile("cp.async.cg.shared.global [%0], [%1], 16;" :: "r"(dst), "l"(src) : "memory");
}
__device__ __forceinline__ void cp16z(uint32_t dst, const void* src, uint32_t srcbytes) {
    asm volatile("cp.async.cg.shared.global [%0], [%1], 16, %2;"
                 :: "r"(dst), "l"(src), "r"(srcbytes) : "memory");
}
__device__ __forceinline__ void ldm_x4(uint32_t* r, uint32_t addr) {
    asm volatile("ldmatrix.sync.aligned.m8n8.x4.shared.b16 {%0,%1,%2,%3}, [%4];"
                 : "=r"(r[0]), "=r"(r[1]), "=r"(r[2]), "=r"(r[3]) : "r"(addr));
}
__device__ __forceinline__ void mma_bf16(float* d, const uint32_t* a, uint32_t b0, uint32_t b1) {
    asm volatile(
        "mma.sync.aligned.m16n8k16.row.col.f32.bf16.bf16.f32 "
        "{%0,%1,%2,%3}, {%4,%5,%6,%7}, {%8,%9}, {%0,%1,%2,%3};"
        : "+f"(d[0]), "+f"(d[1]), "+f"(d[2]), "+f"(d[3])
        : "r"(a[0]), "r"(a[1]), "r"(a[2]), "r"(a[3]), "r"(b0), "r"(b1));
}
__device__ __forceinline__ float sqrt_ap(float x) {
    float r;
    asm("sqrt.approx.f32 %0, %1;" : "=f"(r) : "f"(x));
    return r;
}

// ---------------------------------------------------------------------------
// init: pad s_pts into float4 table; zero counters.  (No C zero needed:
// kp_gather writes every output row.)
// ---------------------------------------------------------------------------
__global__ void kp_init(const float* __restrict__ s_pts, int N) {
    const int i = blockIdx.x * blockDim.x + threadIdx.x;
    if (i < N)
        g_pts4[i] = make_float4(s_pts[3 * i], s_pts[3 * i + 1], s_pts[3 * i + 2], 0.f);
    if (i < 16) g_cnt[i] = 0;
}

// ---------------------------------------------------------------------------
// Stage A (sparse, compacting).  Thread = (query, neighbor) pair; warp = query.
// d^2 prefilter -> ~8% of pairs run the sqrt loop.  Per-k 4-reg accumulation
// over that k's neighbors.  Records kmask + per-k rank for the gather pass.
// ---------------------------------------------------------------------------
__global__ __launch_bounds__(256) void kp_stage1(
    const float* __restrict__ q_pts,
    const void*  __restrict__ inds_raw,
    const float* __restrict__ s_feats,
    const float* __restrict__ kp,
    int M, int N)
{
    __shared__ __align__(16) float w_s[8][HN][16];
    __shared__ float kp_s[KP][3];
    __shared__ int   is64_s;

    const int tid  = threadIdx.x;
    const int warp = tid >> 5;
    const int lane = tid & 31;
    const int m    = blockIdx.x * 8 + warp;

    if (tid == 0) {
        const int* p = (const int*)inds_raw;
        is64_s = (p[1] == 0 && p[3] == 0 && p[5] == 0 && p[7] == 0) ? 1 : 0;
    }
    if (tid < KP * 3) ((float*)kp_s)[tid] = kp[tid];
    __syncthreads();
    const int is64 = is64_s;

    float qc = (lane < 3 && m < M) ? q_pts[m * 3 + lane] : 0.f;
    const float qx = __shfl_sync(0xffffffffu, qc, 0);
    const float qy = __shfl_sync(0xffffffffu, qc, 1);
    const float qz = __shfl_sync(0xffffffffu, qc, 2);

    int ii = 0;
    float nx = 1e6f, ny = 1e6f, nz = 1e6f;
    if (m < M) {
        long long pos = (long long)m * HN + lane;
        long long idx = is64 ? ((const long long*)inds_raw)[pos]
                             : (long long)((const int*)inds_raw)[pos];
        if (idx >= 0 && idx < N) {
            ii = (int)idx;
            float4 p = g_pts4[ii];
            nx = p.x - qx; ny = p.y - qy; nz = p.z - qz;
        }
    }
    const float d2 = nx * nx + ny * ny + nz * nz;
    const bool active = d2 < 7.0226f;            // (1 + 1.65)^2 + eps

    uint32_t kml = 0;
    if (active) {
#pragma unroll
        for (int k = 0; k < KP; k++) {
            float dx = nx - kp_s[k][0];
            float dy = ny - kp_s[k][1];
            float dz = nz - kp_s[k][2];
            float w  = fmaxf(1.f - sqrt_ap(dx * dx + dy * dy + dz * dz), 0.f);
            w_s[warp][lane][k] = w;
            if (w > 0.f) kml |= (1u << k);
        }
    }
    const uint32_t kmask = __reduce_or_sync(0xffffffffu, kml);
    __syncwarp();                                // w_s visible within the warp

    if (m >= M) return;                          // warp-uniform exit
    if (lane == 0) g_kmask[m] = kmask;           // gather needs this for ALL m
    if (kmask == 0) return;

    // per-k rank atomics in one shot: lane k owns counter k; record rank map
    int rank = 0;
    if (lane < KP && ((kmask >> lane) & 1)) {
        rank = atomicAdd(&g_cnt[lane], 1);
        g_rkmap[(size_t)m * 16 + lane] = rank;
    }

    // loop over ACTIVE k; per-k: 4-reg accumulator over that k's neighbors
    uint32_t km = kmask;
    while (km) {
        const int k = __ffs(km) - 1;
        km &= km - 1;
        const int rk = __shfl_sync(0xffffffffu, rank, k);
        uint32_t hm = __ballot_sync(0xffffffffu, (kml >> k) & 1u);

        float a0 = 0.f, a1 = 0.f, a2 = 0.f, a3 = 0.f;
        while (hm) {
            const int h = __ffs(hm) - 1;
            hm &= hm - 1;
            const int iih = __shfl_sync(0xffffffffu, ii, h);
            float4 f = *(const float4*)(s_feats + (long long)iih * CIN + lane * 4);
            const float wk = w_s[warp][h][k];    // broadcast LDS
            a0 += wk * f.x; a1 += wk * f.y; a2 += wk * f.z; a3 += wk * f.w;
        }

        if (rk < MAXR) {                         // defensive clamp vs gemm grid
            float v[4] = { a0, a1, a2, a3 };
            uint32_t hw[4], lw[4];
#pragma unroll
            for (int j = 0; j < 4; j++) {
                __nv_bfloat16 h = __float2bfloat16(v[j]);
                float lo = v[j] - __bfloat162float(h);
                hw[j] = (uint32_t)__bfloat16_as_ushort(h);
                lw[j] = (uint32_t)__bfloat16_as_ushort(__float2bfloat16(lo));
            }
            uint2 ph = make_uint2(hw[0] | (hw[1] << 16), hw[2] | (hw[3] << 16));
            uint2 pl = make_uint2(lw[0] | (lw[1] << 16), lw[2] | (lw[3] << 16));
            const size_t ro = ((size_t)k * CAP + rk) * CIN + lane * 4;
            *(uint2*)(g_a_hi + ro) = ph;
            *(uint2*)(g_a_lo + ro) = pl;
        }
    }
}

// ---------------------------------------------------------------------------
// prep: W -> W^T bf16 hi/lo.
// ---------------------------------------------------------------------------
__global__ void kp_prep(const float* __restrict__ W) {
    const int kk = blockIdx.x;
    const int n  = threadIdx.x;
    float v = W[kk * COUT + n];
    __nv_bfloat16 h = __float2bfloat16(v);
    float lo = v - __bfloat162float(h);
    g_wt_hi[n * KTOT + kk] = h;
    g_wt_lo[n * KTOT + kk] = __float2bfloat16(lo);
}

// ---------------------------------------------------------------------------
// Stage B: per-k gathered GEMM, 64-row tiles, single load phase for full K.
// Epilogue: DENSE store by rank into g_part (plain STG -- no global atomics).
// ---------------------------------------------------------------------------
#define AHI(kb)  ((uint32_t)(kb) * 8192u)             // 2 x 8KB
#define ALO(kb)  (16384u + (uint32_t)(kb) * 8192u)    // 2 x 8KB
#define BHI(kb)  (32768u + (uint32_t)(kb) * 16384u)   // 2 x 16KB
#define BLO(kb)  (65536u + (uint32_t)(kb) * 16384u)   // 2 x 16KB
#define GSMEM    98304                                // 96KB -> 2 CTA/SM

__global__ __launch_bounds__(256, 2) void kp_gemm_sp()
{
    const int k    = blockIdx.y;
    const int rows = g_cnt[k];
    const int t0   = blockIdx.x * TR;
    if (t0 >= rows) return;

    extern __shared__ __align__(1024) char smem[];
    const uint32_t sb = smem_u32(smem);

    const int tid  = threadIdx.x;
    const int wid  = tid >> 5;
    const int lane = tid & 31;
    const int wm   = wid & 3;          // 4 row-blocks of 16
    const int wn   = wid >> 2;         // 2 col-blocks of 64

    const int ar  = tid >> 2;
    const int as0 = (tid & 3) * 2;
    const int br  = tid >> 1;
    const int bs0 = (tid & 1) * 4;

    const uint32_t a_bytes  = (t0 + ar < rows) ? 16u : 0u;
    const size_t   a_base   = ((size_t)k * CAP + t0 + ar) * CIN;
    const size_t   b_base   = (size_t)br * KTOT + (size_t)k * CIN;
    const uint32_t a_sw_row = (uint32_t)(ar & 7) << 4;
    const uint32_t b_sw_row = (uint32_t)(br & 7) << 4;

    float acc[8][4];
#pragma unroll
    for (int j = 0; j < 8; j++)
#pragma unroll
        for (int q = 0; q < 4; q++) acc[j][q] = 0.f;

    // single load phase: everything, one commit
#pragma unroll
    for (int kb = 0; kb < 2; kb++) {
#pragma unroll
        for (int p = 0; p < 2; p++) {
            const int sec = as0 + p;
            const uint32_t so = ar * 128 + ((uint32_t)(sec * 16) ^ a_sw_row);
            cp16z(sb + AHI(kb) + so, g_a_hi + a_base + kb * 64 + sec * 8, a_bytes);
            cp16z(sb + ALO(kb) + so, g_a_lo + a_base + kb * 64 + sec * 8, a_bytes);
        }
#pragma unroll
        for (int p = 0; p < 4; p++) {
            const int sec = bs0 + p;
            const uint32_t so = br * 128 + ((uint32_t)(sec * 16) ^ b_sw_row);
            cp16(sb + BHI(kb) + so, g_wt_hi + b_base + kb * 64 + sec * 8);
            cp16(sb + BLO(kb) + so, g_wt_lo + b_base + kb * 64 + sec * 8);
        }
    }
    asm volatile("cp.async.commit_group;" ::: "memory");
    asm volatile("cp.async.wait_group 0;" ::: "memory");
    __syncthreads();

    const int j  = lane >> 3;
    const int l8 = lane & 7;

#pragma unroll
    for (int kb = 0; kb < 2; kb++) {
#pragma unroll
        for (int ks = 0; ks < 4; ks++) {
            const int arow = wm * 16 + (j & 1) * 8 + l8;
            const uint32_t abyte = (uint32_t)((j >> 1) * 16 + ks * 32);
            const uint32_t aso = arow * 128 + (abyte ^ ((uint32_t)(arow & 7) << 4));
            uint32_t ah[4], al[4];
            ldm_x4(ah, sb + AHI(kb) + aso);
            ldm_x4(al, sb + ALO(kb) + aso);

            uint32_t bh[4][4], bl[4][4];
#pragma unroll
            for (int nt = 0; nt < 4; nt++) {
                const int brow = wn * 64 + nt * 16 + (j >> 1) * 8 + l8;
                const uint32_t bbyte = (uint32_t)((j & 1) * 16 + ks * 32);
                const uint32_t bso = brow * 128 + (bbyte ^ ((uint32_t)(brow & 7) << 4));
                ldm_x4(bh[nt], sb + BHI(kb) + bso);
                ldm_x4(bl[nt], sb + BLO(kb) + bso);
            }

#pragma unroll
            for (int n8 = 0; n8 < 8; n8++) {
                const uint32_t bh0 = bh[n8 >> 1][(n8 & 1) * 2];
                const uint32_t bh1 = bh[n8 >> 1][(n8 & 1) * 2 + 1];
                const uint32_t bl0 = bl[n8 >> 1][(n8 & 1) * 2];
                const uint32_t bl1 = bl[n8 >> 1][(n8 & 1) * 2 + 1];
                mma_bf16(acc[n8], ah, bh0, bh1);   // hi * hi
                mma_bf16(acc[n8], ah, bl0, bl1);   // hi * lo
                mma_bf16(acc[n8], al, bh0, bh1);   // lo * hi
            }
        }
    }

    // dense epilogue: STG partials by rank (no atomics)
    const int qrow = lane >> 2;
    const int qcol = (lane & 3) * 2;
    const int r0 = wm * 16 + qrow;
    const int r1 = r0 + 8;
    float* p0 = g_part + ((size_t)k * CAP + t0 + r0) * COUT;
    float* p1 = g_part + ((size_t)k * CAP + t0 + r1) * COUT;
    const bool ok0 = (t0 + r0 < rows);
    const bool ok1 = (t0 + r1 < rows);
#pragma unroll
    for (int n8 = 0; n8 < 8; n8++) {
        const int col = wn * 64 + n8 * 8 + qcol;
        if (ok0) *(float2*)(p0 + col) = make_float2(acc[n8][0], acc[n8][1]);
        if (ok1) *(float2*)(p1 + col) = make_float2(acc[n8][2], acc[n8][3]);
    }
}

// ---------------------------------------------------------------------------
// Gather: warp per query sums its active k-planes from g_part -> C.
// Writes EVERY row (zeros if no active plane), so C needs no pre-zeroing.
// ---------------------------------------------------------------------------
__global__ __launch_bounds__(256) void kp_gather(float* __restrict__ C, int M)
{
    const int m    = blockIdx.x * 8 + (threadIdx.x >> 5);
    const int lane = threadIdx.x & 31;
    if (m >= M) return;

    uint32_t km = g_kmask[m];
    float4 a = make_float4(0.f, 0.f, 0.f, 0.f);
    while (km) {
        const int k = __ffs(km) - 1;
        km &= km - 1;
        const int rk = g_rkmap[(size_t)m * 16 + k];
        if (rk < MAXR) {
            const float4 v = *(const float4*)(g_part + ((size_t)k * CAP + rk) * COUT
                                              + lane * 4);
            a.x += v.x; a.y += v.y; a.z += v.z; a.w += v.w;
        }
    }
    *(float4*)(C + (size_t)m * COUT + lane * 4) = a;
}

// ---------------------------------------------------------------------------
extern "C" void kernel_launch(void* const* d_in, const int* in_sizes, int n_in,
                              void* d_out, int out_size)
{
    const float* q_pts   = (const float*)d_in[0];
    const float* s_pts   = (const float*)d_in[1];
    const float* s_feats = (const float*)d_in[2];
    const void*  inds    = d_in[3];
    const float* kp      = (const float*)d_in[4];
    const float* W       = (const float*)d_in[5];

    int M = in_sizes[0] / 3;
    int N = in_sizes[1] / 3;
    if (M > M_MAX) M = M_MAX;

    static int smem_set = 0;
    if (!smem_set) {
        cudaFuncSetAttribute(kp_gemm_sp, cudaFuncAttributeMaxDynamicSharedMemorySize,
                             GSMEM);
        smem_set = 1;
    }

    kp_init<<<(N + 255) / 256, 256>>>(s_pts, N);
    kp_stage1<<<(M + 7) / 8, 256>>>(q_pts, inds, s_feats, kp, M, N);
    kp_prep<<<KTOT, COUT>>>(W);
    kp_gemm_sp<<<dim3(GRIDX, KP), 256, GSMEM>>>();
    kp_gather<<<(M + 7) / 8, 256>>>((float*)d_out, M);
}

// round 17
// speedup vs baseline: 1.2265x; 1.2265x over previous
#include <cuda_runtime.h>
#include <cuda_bf16.h>
#include <cstdint>

#define HN    32
#define KP    15
#define CIN   128
#define COUT  128
#define KTOT  1920          // KP * CIN
#define M_MAX 50000
#define CAP   50176         // per-k capacity (row stride in compacted buffers)
#define GRIDX 160           // gemm x-tiles per k (10240 rows >> max possible ~6700)
#define TR    64            // gemm tile rows
#define MAXR  (GRIDX * TR)  // rows the gemm can consume per k

// ---- device scratch (static __device__ arrays: the sanctioned no-alloc path) ----
__device__ __nv_bfloat16 g_a_hi[(size_t)KP * CAP * CIN];  // compacted hi rows
__device__ __nv_bfloat16 g_a_lo[(size_t)KP * CAP * CIN];  // compacted lo rows
__device__ int           g_idx[(size_t)KP * CAP];         // query index per compacted row
__device__ int           g_cnt[16];                       // rows appended per k
__device__ __nv_bfloat16 g_wt_hi[COUT * KTOT];            // W^T [d][kk] bf16 hi
__device__ __nv_bfloat16 g_wt_lo[COUT * KTOT];            // W^T [d][kk] bf16 lo
__device__ float4        g_pts4[CAP];                     // padded support points

__device__ __forceinline__ uint32_t smem_u32(const void* p) {
    uint32_t a;
    asm("{ .reg .u64 t; cvta.to.shared.u64 t, %1; cvt.u32.u64 %0, t; }" : "=r"(a) : "l"(p));
    return a;
}
__device__ __forceinline__ void cp16(uint32_t dst, const void* src) {
    asm volatile("cp.async.cg.shared.global [%0], [%1], 16;" :: "r"(dst), "l"(src) : "memory");
}
__device__ __forceinline__ void cp16z(uint32_t dst, const void* src, uint32_t srcbytes) {
    asm volatile("cp.async.cg.shared.global [%0], [%1], 16, %2;"
                 :: "r"(dst), "l"(src), "r"(srcbytes) : "memory");
}
__device__ __forceinline__ void ldm_x4(uint32_t* r, uint32_t addr) {
    asm volatile("ldmatrix.sync.aligned.m8n8.x4.shared.b16 {%0,%1,%2,%3}, [%4];"
                 : "=r"(r[0]), "=r"(r[1]), "=r"(r[2]), "=r"(r[3]) : "r"(addr));
}
__device__ __forceinline__ void mma_bf16(float* d, const uint32_t* a, uint32_t b0, uint32_t b1) {
    asm volatile(
        "mma.sync.aligned.m16n8k16.row.col.f32.bf16.bf16.f32 "
        "{%0,%1,%2,%3}, {%4,%5,%6,%7}, {%8,%9}, {%0,%1,%2,%3};"
        : "+f"(d[0]), "+f"(d[1]), "+f"(d[2]), "+f"(d[3])
        : "r"(a[0]), "r"(a[1]), "r"(a[2]), "r"(a[3]), "r"(b0), "r"(b1));
}
__device__ __forceinline__ void red2(float* p, float a, float b) {
    asm volatile("red.global.add.v2.f32 [%0], {%1, %2};" :: "l"(p), "f"(a), "f"(b) : "memory");
}
__device__ __forceinline__ float sqrt_ap(float x) {
    float r;
    asm("sqrt.approx.f32 %0, %1;" : "=f"(r) : "f"(x));
    return r;
}

// ---------------------------------------------------------------------------
// init: pad s_pts into float4 table; zero counters AND C.
// ---------------------------------------------------------------------------
__global__ void kp_init(const float* __restrict__ s_pts, float* __restrict__ C,
                        int N, int total4) {
    const int i = blockIdx.x * blockDim.x + threadIdx.x;
    if (i < N)
        g_pts4[i] = make_float4(s_pts[3 * i], s_pts[3 * i + 1], s_pts[3 * i + 2], 0.f);
    if (i < 16) g_cnt[i] = 0;
    if (i < total4)
        ((float4*)C)[i] = make_float4(0.f, 0.f, 0.f, 0.f);
}

// ---------------------------------------------------------------------------
// Stage A (sparse, compacting).  Thread = (query, neighbor) pair; warp = query.
// ---------------------------------------------------------------------------
__global__ __launch_bounds__(256) void kp_stage1(
    const float* __restrict__ q_pts,
    const void*  __restrict__ inds_raw,
    const float* __restrict__ s_feats,
    const float* __restrict__ kp,
    int M, int N)
{
    __shared__ __align__(16) float w_s[8][HN][16];
    __shared__ float kp_s[KP][3];
    __shared__ int   is64_s;

    const int tid  = threadIdx.x;
    const int warp = tid >> 5;
    const int lane = tid & 31;
    const int m    = blockIdx.x * 8 + warp;

    if (tid == 0) {
        const int* p = (const int*)inds_raw;
        is64_s = (p[1] == 0 && p[3] == 0 && p[5] == 0 && p[7] == 0) ? 1 : 0;
    }
    if (tid < KP * 3) ((float*)kp_s)[tid] = kp[tid];
    __syncthreads();
    const int is64 = is64_s;

    float qc = (lane < 3 && m < M) ? q_pts[m * 3 + lane] : 0.f;
    const float qx = __shfl_sync(0xffffffffu, qc, 0);
    const float qy = __shfl_sync(0xffffffffu, qc, 1);
    const float qz = __shfl_sync(0xffffffffu, qc, 2);

    int ii = 0;
    float nx = 1e6f, ny = 1e6f, nz = 1e6f;
    if (m < M) {
        long long pos = (long long)m * HN + lane;
        long long idx = is64 ? ((const long long*)inds_raw)[pos]
                             : (long long)((const int*)inds_raw)[pos];
        if (idx >= 0 && idx < N) {
            ii = (int)idx;
            float4 p = g_pts4[ii];
            nx = p.x - qx; ny = p.y - qy; nz = p.z - qz;
        }
    }
    const float d2 = nx * nx + ny * ny + nz * nz;
    const bool active = d2 < 7.0226f;            // (1 + 1.65)^2 + eps

    uint32_t kml = 0;
    if (active) {
#pragma unroll
        for (int k = 0; k < KP; k++) {
            float dx = nx - kp_s[k][0];
            float dy = ny - kp_s[k][1];
            float dz = nz - kp_s[k][2];
            float w  = fmaxf(1.f - sqrt_ap(dx * dx + dy * dy + dz * dz), 0.f);
            w_s[warp][lane][k] = w;
            if (w > 0.f) kml |= (1u << k);
        }
    }
    const uint32_t kmask = __reduce_or_sync(0xffffffffu, kml);
    __syncwarp();                                // w_s visible within the warp

    if (m >= M) return;                          // warp-uniform exit
    if (kmask == 0) return;

    // per-k rank atomics in one shot: lane k owns counter k
    int rank = 0;
    if (lane < KP && ((kmask >> lane) & 1))
        rank = atomicAdd(&g_cnt[lane], 1);

    // loop over ACTIVE k; per-k: 4-reg accumulator over that k's neighbors
    uint32_t km = kmask;
    while (km) {
        const int k = __ffs(km) - 1;
        km &= km - 1;
        const int rk = __shfl_sync(0xffffffffu, rank, k);
        uint32_t hm = __ballot_sync(0xffffffffu, (kml >> k) & 1u);

        float a0 = 0.f, a1 = 0.f, a2 = 0.f, a3 = 0.f;
        while (hm) {
            const int h = __ffs(hm) - 1;
            hm &= hm - 1;
            const int iih = __shfl_sync(0xffffffffu, ii, h);
            float4 f = *(const float4*)(s_feats + (long long)iih * CIN + lane * 4);
            const float wk = w_s[warp][h][k];    // broadcast LDS
            a0 += wk * f.x; a1 += wk * f.y; a2 += wk * f.z; a3 += wk * f.w;
        }

        if (rk < MAXR) {                         // defensive clamp vs gemm grid
            float v[4] = { a0, a1, a2, a3 };
            uint32_t hw[4], lw[4];
#pragma unroll
            for (int j = 0; j < 4; j++) {
                __nv_bfloat16 h = __float2bfloat16(v[j]);
                float lo = v[j] - __bfloat162float(h);
                hw[j] = (uint32_t)__bfloat16_as_ushort(h);
                lw[j] = (uint32_t)__bfloat16_as_ushort(__float2bfloat16(lo));
            }
            uint2 ph = make_uint2(hw[0] | (hw[1] << 16), hw[2] | (hw[3] << 16));
            uint2 pl = make_uint2(lw[0] | (lw[1] << 16), lw[2] | (lw[3] << 16));
            const size_t ro = ((size_t)k * CAP + rk) * CIN + lane * 4;
            *(uint2*)(g_a_hi + ro) = ph;
            *(uint2*)(g_a_lo + ro) = pl;
            if (lane == 0) g_idx[(size_t)k * CAP + rk] = m;
        }
    }
}

// ---------------------------------------------------------------------------
// prep: W -> W^T bf16 hi/lo.
// ---------------------------------------------------------------------------
__global__ void kp_prep(const float* __restrict__ W) {
    const int kk = blockIdx.x;
    const int n  = threadIdx.x;
    float v = W[kk * COUT + n];
    __nv_bfloat16 h = __float2bfloat16(v);
    float lo = v - __bfloat162float(h);
    g_wt_hi[n * KTOT + kk] = h;
    g_wt_lo[n * KTOT + kk] = __float2bfloat16(lo);
}

// ---------------------------------------------------------------------------
// Stage B: per-k gathered GEMM, N-SPLIT: blockIdx.z selects 64 of 128 output
// cols, halving B smem -> 64KB total -> 3 CTAs/SM (was 2).  64-row tiles,
// single load phase for full K (one commit/wait/sync), 3 split passes.
// Scatter-accumulate via red.global.add.v2.f32.
// ---------------------------------------------------------------------------
#define AHI(kb)  ((uint32_t)(kb) * 8192u)             // 2 x 8KB
#define ALO(kb)  (16384u + (uint32_t)(kb) * 8192u)    // 2 x 8KB
#define BHI(kb)  (32768u + (uint32_t)(kb) * 8192u)    // 2 x 8KB  (64 cols only)
#define BLO(kb)  (49152u + (uint32_t)(kb) * 8192u)    // 2 x 8KB
#define GSMEM    65536                                // 64KB -> 3 CTA/SM

__global__ __launch_bounds__(256, 3) void kp_gemm_sp(float* __restrict__ C)
{
    const int k    = blockIdx.y;
    const int rows = g_cnt[k];
    const int t0   = blockIdx.x * TR;
    if (t0 >= rows) return;
    const int ncta = blockIdx.z;       // 0/1: which 64-col half of the output

    extern __shared__ __align__(1024) char smem[];
    const uint32_t sb = smem_u32(smem);

    const int tid  = threadIdx.x;
    const int wid  = tid >> 5;
    const int lane = tid & 31;
    const int wm   = wid & 3;          // 4 row-blocks of 16
    const int wn   = wid >> 2;         // 2 col-blocks of 32 (within the 64)

    // A-load: row = tid>>2 (0..63), two 16B sectors (tid&3)*2+{0,1}
    const int ar  = tid >> 2;
    const int as0 = (tid & 3) * 2;
    // B-load: same shape (64 rows of W^T = our 64 output cols)
    const int br  = ar;
    const int bs0 = as0;

    const uint32_t a_bytes  = (t0 + ar < rows) ? 16u : 0u;
    const size_t   a_base   = ((size_t)k * CAP + t0 + ar) * CIN;
    const size_t   b_base   = (size_t)(ncta * 64 + br) * KTOT + (size_t)k * CIN;
    const uint32_t a_sw_row = (uint32_t)(ar & 7) << 4;

    float acc[4][4];
#pragma unroll
    for (int j = 0; j < 4; j++)
#pragma unroll
        for (int q = 0; q < 4; q++) acc[j][q] = 0.f;

    // single load phase: everything, one commit
#pragma unroll
    for (int kb = 0; kb < 2; kb++) {
#pragma unroll
        for (int p = 0; p < 2; p++) {
            const int sec = as0 + p;
            const uint32_t so = ar * 128 + ((uint32_t)(sec * 16) ^ a_sw_row);
            cp16z(sb + AHI(kb) + so, g_a_hi + a_base + kb * 64 + sec * 8, a_bytes);
            cp16z(sb + ALO(kb) + so, g_a_lo + a_base + kb * 64 + sec * 8, a_bytes);
            cp16(sb + BHI(kb) + so, g_wt_hi + b_base + kb * 64 + sec * 8);
            cp16(sb + BLO(kb) + so, g_wt_lo + b_base + kb * 64 + sec * 8);
        }
    }
    asm volatile("cp.async.commit_group;" ::: "memory");
    asm volatile("cp.async.wait_group 0;" ::: "memory");
    __syncthreads();

    const int j  = lane >> 3;
    const int l8 = lane & 7;

#pragma unroll
    for (int kb = 0; kb < 2; kb++) {
#pragma unroll
        for (int ks = 0; ks < 4; ks++) {
            const int arow = wm * 16 + (j & 1) * 8 + l8;
            const uint32_t abyte = (uint32_t)((j >> 1) * 16 + ks * 32);
            const uint32_t aso = arow * 128 + (abyte ^ ((uint32_t)(arow & 7) << 4));
            uint32_t ah[4], al[4];
            ldm_x4(ah, sb + AHI(kb) + aso);
            ldm_x4(al, sb + ALO(kb) + aso);

            uint32_t bh[2][4], bl[2][4];
#pragma unroll
            for (int nt = 0; nt < 2; nt++) {
                const int brow = wn * 32 + nt * 16 + (j >> 1) * 8 + l8;
                const uint32_t bbyte = (uint32_t)((j & 1) * 16 + ks * 32);
                const uint32_t bso = brow * 128 + (bbyte ^ ((uint32_t)(brow & 7) << 4));
                ldm_x4(bh[nt], sb + BHI(kb) + bso);
                ldm_x4(bl[nt], sb + BLO(kb) + bso);
            }

#pragma unroll
            for (int n8 = 0; n8 < 4; n8++) {
                const uint32_t bh0 = bh[n8 >> 1][(n8 & 1) * 2];
                const uint32_t bh1 = bh[n8 >> 1][(n8 & 1) * 2 + 1];
                const uint32_t bl0 = bl[n8 >> 1][(n8 & 1) * 2];
                const uint32_t bl1 = bl[n8 >> 1][(n8 & 1) * 2 + 1];
                mma_bf16(acc[n8], ah, bh0, bh1);   // hi * hi
                mma_bf16(acc[n8], ah, bl0, bl1);   // hi * lo
                mma_bf16(acc[n8], al, bh0, bh1);   // lo * hi
            }
        }
    }

    // scatter-accumulate epilogue (64 cols per CTA)
    const int qrow = lane >> 2;
    const int qcol = (lane & 3) * 2;
    const int r0 = wm * 16 + qrow;
    const int r1 = r0 + 8;
    const bool ok0 = (t0 + r0 < rows);
    const bool ok1 = (t0 + r1 < rows);
    const int mi0 = ok0 ? g_idx[(size_t)k * CAP + t0 + r0] : 0;
    const int mi1 = ok1 ? g_idx[(size_t)k * CAP + t0 + r1] : 0;
#pragma unroll
    for (int n8 = 0; n8 < 4; n8++) {
        const int col = ncta * 64 + wn * 32 + n8 * 8 + qcol;
        if (ok0) red2(C + (size_t)mi0 * COUT + col, acc[n8][0], acc[n8][1]);
        if (ok1) red2(C + (size_t)mi1 * COUT + col, acc[n8][2], acc[n8][3]);
    }
}

// ---------------------------------------------------------------------------
extern "C" void kernel_launch(void* const* d_in, const int* in_sizes, int n_in,
                              void* d_out, int out_size)
{
    const float* q_pts   = (const float*)d_in[0];
    const float* s_pts   = (const float*)d_in[1];
    const float* s_feats = (const float*)d_in[2];
    const void*  inds    = d_in[3];
    const float* kp      = (const float*)d_in[4];
    const float* W       = (const float*)d_in[5];

    int M = in_sizes[0] / 3;
    int N = in_sizes[1] / 3;
    if (M > M_MAX) M = M_MAX;

    static int smem_set = 0;
    if (!smem_set) {
        cudaFuncSetAttribute(kp_gemm_sp, cudaFuncAttributeMaxDynamicSharedMemorySize,
                             GSMEM);
        smem_set = 1;
    }

    const int total4 = M * COUT / 4;
    const int initg  = (total4 + 255) / 256;
    kp_init<<<initg, 256>>>(s_pts, (float*)d_out, N, total4);
    kp_stage1<<<(M + 7) / 8, 256>>>(q_pts, inds, s_feats, kp, M, N);
    kp_prep<<<KTOT, COUT>>>(W);
    kp_gemm_sp<<<dim3(GRIDX, KP, 2), 256, GSMEM>>>((float*)d_out);
}